// round 10
// baseline (speedup 1.0000x reference)
#include <cuda_runtime.h>
#include <cstdint>

// RBDispatcher — single-launch hybrid: source-centric s1 half (exact dedup
// via binary search on the SORTED idx_s1, zero scratch/atomics) + direct
// gather s2 half.
//
//   out[r]        = x[ idx_s1[ s1_to_s2[r] ] / TOP_K ]   r in [0, N_S2)
//   out[N_S2 + i] = x[ idx_s1[i] / TOP_K ]               i in [0, N_S1)
//
// Since idx_s1 is sorted, the s1-half destinations of source token s are the
// contiguous index range { i : idx_s1[i] in [2s, 2s+2) }. One CTA per token
// binary-searches that range, reads the 8KiB row ONCE, and stores it to each
// (contiguous!) destination from registers. The s2 half stays a plain gather
// (random map; reads ~90% L2-hit thanks to streaming stores keeping x
// resident). R9's 3-launch inversion lost to launch overhead; this is the
// same traffic cut in ONE launch.
//
// Indices are int32 on device (JAX demotes int64 without x64).

static constexpr int D_MODEL  = 2048;
static constexpr int TOP_K    = 2;
static constexpr int VECS     = D_MODEL / 4;   // 512 float4 per row
static constexpr int NT       = 256;
static constexpr int N_TOKENS = 8192;          // source rows in x

__device__ __forceinline__ int lower_bound_i32(const int* __restrict__ a,
                                               int n, int key)
{
    // first index with a[i] >= key; uniform across CTA (broadcast loads)
    int lo = 0, hi = n;
    while (lo < hi) {
        int mid = (lo + hi) >> 1;
        if (__ldg(&a[mid]) < key) lo = mid + 1;
        else hi = mid;
    }
    return lo;
}

__global__ __launch_bounds__(NT, 8)
void rb_hybrid_kernel(const float4* __restrict__ x,
                      const int* __restrict__ idx_s1,
                      const int* __restrict__ s1_to_s2,
                      float4* __restrict__ out,
                      int n_s1, int n_s2)
{
    const int b = blockIdx.x;
    const int t = threadIdx.x;

    if (b < N_TOKENS) {
        // ---- source-centric: s1 half ----
        const int src = b;
        const int lo = lower_bound_i32(idx_s1, n_s1, 2 * src);
        const int hi = lower_bound_i32(idx_s1, n_s1, 2 * src + 2);
        if (lo == hi) return;                      // token dropped / unused

        const float4* __restrict__ srcp = x + (long long)src * VECS;
        // Read the 8 KiB row ONCE.
        float4 a0 = __ldg(&srcp[t]);
        float4 a1 = __ldg(&srcp[t + NT]);

        // Destinations are contiguous output rows n_s2+lo .. n_s2+hi-1.
        float4* __restrict__ dst = out + (long long)(n_s2 + lo) * VECS;
        for (int i = lo; i < hi; i++, dst += VECS) {
            __stcs(&dst[t],      a0);
            __stcs(&dst[t + NT], a1);
        }
    } else {
        // ---- gather: s2 half, 2 rows per CTA ----
        const int row0 = (b - N_TOKENS) * 2;       // in [0, n_s2)
        const int row1 = row0 + 1;

        const int s0 = __ldg(&idx_s1[__ldg(&s1_to_s2[row0])]) / TOP_K;
        const int s1 = __ldg(&idx_s1[__ldg(&s1_to_s2[row1])]) / TOP_K;

        const float4* __restrict__ src0 = x + (long long)s0 * VECS;
        const float4* __restrict__ src1 = x + (long long)s1 * VECS;
        float4* __restrict__ dst0 = out + (long long)row0 * VECS;
        float4* __restrict__ dst1 = dst0 + VECS;

        // Batch loads, then stores (R4's proven pattern).
        float4 a0 = __ldg(&src0[t]);
        float4 a1 = __ldg(&src0[t + NT]);
        float4 b0 = __ldg(&src1[t]);
        float4 b1 = __ldg(&src1[t + NT]);

        // Streaming stores keep x (64 MiB) L2-resident.
        __stcs(&dst0[t],      a0);
        __stcs(&dst0[t + NT], a1);
        __stcs(&dst1[t],      b0);
        __stcs(&dst1[t + NT], b1);
    }
}

extern "C" void kernel_launch(void* const* d_in, const int* in_sizes, int n_in,
                              void* d_out, int out_size)
{
    const float4* x        = (const float4*)d_in[0];
    const int*    idx_s1   = (const int*)d_in[1];
    const int*    s1_to_s2 = (const int*)d_in[2];

    const int n_s1 = in_sizes[1];        // 16384
    const int n_s2 = in_sizes[2];        // 8192 (even)

    const int n_ctas = N_TOKENS + n_s2 / 2;  // 8192 + 4096

    rb_hybrid_kernel<<<n_ctas, NT>>>(
        x, idx_s1, s1_to_s2, (float4*)d_out, n_s1, n_s2);
}

// round 11
// speedup vs baseline: 1.1626x; 1.1626x over previous
#include <cuda_runtime.h>
#include <cstdint>

// RBDispatcher — R11: 4-slot run-dedup, single launch, no search.
//
//   out[r]        = x[ idx_s1[ s1_to_s2[r] ] / TOP_K ]   r in [0, N_S2)
//   out[N_S2 + i] = x[ idx_s1[i] / TOP_K ]               i in [0, N_S1)
//
// Model (R3-R10): LTS-slice work ~= SM reads + SM writes + writebacks ~=
// 623MB at the ~12-13TB/s NAT LTS cap -> L2 binds, DRAM (67%) and issue (9%)
// idle. Only cuttable term: SM reads. idx_s1 is SORTED (~Poisson(2) runs),
// so a CTA owning 4 CONSECUTIVE s1 slots dedups by adjacent equality -- no
// binary search (R10's serial-latency disaster), no atomics, no scratch.
// Expected unique rows/window ~2.3 of 4 -> s1-half reads drop ~43%.
//
// Indices are int32 on device (JAX demotes int64 without x64).

static constexpr int D_MODEL  = 2048;
static constexpr int TOP_K    = 2;
static constexpr int VECS     = D_MODEL / 4;   // 512 float4 per row
static constexpr int NT       = 512;           // 1 float4 per thread per row
static constexpr int ROWS     = 4;             // rows (slots) per CTA

__global__ __launch_bounds__(NT, 4)
void rb_dispatch_kernel(const float4* __restrict__ x,
                        const int* __restrict__ idx_s1,
                        const int* __restrict__ s1_to_s2,
                        float4* __restrict__ out,
                        int n_s2, int n_s1)
{
    const int t = threadIdx.x;
    const int n_s2_blks = n_s2 / ROWS;           // 2048

    int s[ROWS];
    float4* dst;

    if (blockIdx.x < (unsigned)n_s2_blks) {
        // ---- s2 half: 4 random rows, no dedup value ----
        const int row0 = blockIdx.x * ROWS;
        #pragma unroll
        for (int j = 0; j < ROWS; j++)
            s[j] = __ldg(&idx_s1[__ldg(&s1_to_s2[row0 + j])]) / TOP_K;
        dst = out + (long long)row0 * VECS;

        float4 v[ROWS];
        #pragma unroll
        for (int j = 0; j < ROWS; j++)
            v[j] = __ldg(&x[(long long)s[j] * VECS + t]);
        #pragma unroll
        for (int j = 0; j < ROWS; j++)
            __stcs(&dst[(long long)j * VECS + t], v[j]);
    } else {
        // ---- s1 half: 4 CONSECUTIVE sorted slots -> run dedup ----
        const int slot0 = (blockIdx.x - n_s2_blks) * ROWS;
        #pragma unroll
        for (int j = 0; j < ROWS; j++)
            s[j] = __ldg(&idx_s1[slot0 + j]) / TOP_K;
        dst = out + (long long)(n_s2 + slot0) * VECS;

        float4 v[ROWS];
        v[0] = __ldg(&x[(long long)s[0] * VECS + t]);
        #pragma unroll
        for (int j = 1; j < ROWS; j++) {
            if (s[j] == s[j - 1]) v[j] = v[j - 1];   // run: reuse register
            else v[j] = __ldg(&x[(long long)s[j] * VECS + t]);
        }
        // Streaming stores: evict-first keeps x (64 MiB) L2-resident, so
        // residual reads stay ~90% L2-hit; DRAM bill is writes.
        #pragma unroll
        for (int j = 0; j < ROWS; j++)
            __stcs(&dst[(long long)j * VECS + t], v[j]);
    }
}

extern "C" void kernel_launch(void* const* d_in, const int* in_sizes, int n_in,
                              void* d_out, int out_size)
{
    const float4* x        = (const float4*)d_in[0];
    const int*    idx_s1   = (const int*)d_in[1];
    const int*    s1_to_s2 = (const int*)d_in[2];

    const int n_s1 = in_sizes[1];        // 16384 (divisible by 4)
    const int n_s2 = in_sizes[2];        // 8192  (divisible by 4)

    const int n_ctas = (n_s2 + n_s1) / ROWS;   // 6144

    rb_dispatch_kernel<<<n_ctas, NT>>>(
        x, idx_s1, s1_to_s2, (float4*)d_out, n_s2, n_s1);
}